// round 2
// baseline (speedup 1.0000x reference)
#include <cuda_runtime.h>
#include <math.h>

#define BB   64
#define CI   16
#define LEN  8192
#define N0   64
#define F0   33
#define T0   128
#define N1   256
#define F1   129
#define T1   32
#define CO   32

// -------- scratch (device globals; no runtime allocation) --------
__device__ float2 g_p0[BB * T0 * F0 * CI];   // (b,t,f,c) complex, 34.6 MB
__device__ float2 g_p1[BB * T1 * F1 * CI];   // (b,t,f1,c) complex, 33.8 MB  (becomes acc1)
__device__ float2 g_out1[BB * T1 * F1 * CO]; // head1 spectrum, 67.6 MB
__device__ float4 g_stats[2 * BB];           // per (head,b): scale, shift_re, shift_im

// ================= STFT n=64 : block per (b,t) =================
__global__ void k_stft0(const float* __restrict__ x) {
    int b = blockIdx.x >> 7;
    int t = blockIdx.x & 127;
    __shared__ float  sx[CI * N0];
    __shared__ float2 tw[N0];
    int tid = threadIdx.x;
    if (tid < N0) {
        float s, c; sincospif(tid * (1.0f / 32.0f), &s, &c);
        tw[tid] = make_float2(c, s);
    }
    for (int i = tid; i < CI * N0; i += 256) {
        int c = i >> 6, s = i & 63;
        int src = t * N0 + s - 32;
        if (src < 0) src = -src;
        if (src >= LEN) src = 2 * LEN - 2 - src;
        sx[i] = x[(b * CI + c) * LEN + src];
    }
    __syncthreads();
    int frame = (b * T0 + t) * (F0 * CI);
    for (int idx = tid; idx < F0 * CI; idx += 256) {
        int f = idx >> 4, c = idx & 15;
        const float* xc = sx + (c << 6);
        float re = 0.f, im = 0.f;
        #pragma unroll 8
        for (int s = 0; s < N0; s++) {
            float2 w = tw[(f * s) & 63];
            re += xc[s] * w.x;
            im -= xc[s] * w.y;
        }
        g_p0[frame + idx] = make_float2(re, im);
    }
}

// ================= STFT n=256 : block per (b,t), s<->(n-s) symmetry =================
__global__ void k_stft1(const float* __restrict__ x) {
    int b = blockIdx.x >> 5;
    int t = blockIdx.x & 31;
    __shared__ float  sx[CI * N1];       // 16 KB
    __shared__ float  su[CI * 129];      // u[s]=x[s]+x[256-s]; su[c*129+0]=x0, +128=x128
    __shared__ float  sv[CI * 129];      // v[s]=x[s]-x[256-s] (padded pitch 129)
    __shared__ float2 tw[N1];
    int tid = threadIdx.x;
    if (tid < N1) {
        float s, c; sincospif(tid * (1.0f / 128.0f), &s, &c);
        tw[tid] = make_float2(c, s);
    }
    for (int i = tid; i < CI * N1; i += 256) {
        int c = i >> 8, s = i & 255;
        int src = t * N1 + s - 128;
        if (src < 0) src = -src;
        if (src >= LEN) src = 2 * LEN - 2 - src;
        sx[i] = x[(b * CI + c) * LEN + src];
    }
    __syncthreads();
    for (int i = tid; i < CI * 128; i += 256) {
        int c = i >> 7, s = i & 127;
        if (s == 0) {
            su[c * 129 + 0]   = sx[(c << 8)];
            su[c * 129 + 128] = sx[(c << 8) + 128];
            sv[c * 129 + 0]   = 0.f;
        } else {
            float a = sx[(c << 8) + s];
            float d = sx[(c << 8) + 256 - s];
            su[c * 129 + s] = a + d;
            sv[c * 129 + s] = a - d;
        }
    }
    __syncthreads();
    int frame = (b * T1 + t) * (F1 * CI);
    for (int idx = tid; idx < F1 * CI; idx += 256) {
        int f = idx >> 4, c = idx & 15;
        const float* u = su + c * 129;
        const float* v = sv + c * 129;
        float re = u[0] + ((f & 1) ? -u[128] : u[128]);
        float im = 0.f;
        #pragma unroll 4
        for (int s = 1; s < 128; s++) {
            float2 w = tw[(f * s) & 255];
            re += u[s] * w.x;
            im -= v[s] * w.y;
        }
        g_p1[frame + idx] = make_float2(re, im);
    }
}

// ================= attention merge : writes directly into p1 (acc1) =================
__global__ void k_merge(const float* __restrict__ mk_r, const float* __restrict__ mk_i,
                        const float* __restrict__ mb_r, const float* __restrict__ mb_i) {
    __shared__ float skr[16], ski[16], sbr[4], sbi[4];
    int tid = threadIdx.x;
    if (tid < 16) { skr[tid] = mk_r[tid]; ski[tid] = mk_i[tid]; }
    if (tid < 4)  { sbr[tid] = mb_r[tid]; sbi[tid] = mb_i[tid]; }
    __syncthreads();
    int g = blockIdx.x * 256 + tid;
    if (g >= BB * T1 * F0 * CI) return;
    int c  = g & 15;
    int f  = (g >> 4) % F0;
    int bt = (g >> 4) / F0;          // b*32 + t
    int t  = bt & 31, b = bt >> 5;

    int base = ((b * T0 + 4 * t) * F0 + f) * CI + c;
    float2 pm[4];
    #pragma unroll
    for (int r = 0; r < 4; r++) pm[r] = g_p0[base + r * (F0 * CI)];

    float av[4];
    #pragma unroll
    for (int s = 0; s < 4; s++) {
        float ar = sbr[s], ai = sbi[s];
        #pragma unroll
        for (int r = 0; r < 4; r++) {
            float kr = skr[r * 4 + s], ki = ski[r * 4 + s];
            ar += pm[r].x * kr - pm[r].y * ki;
            ai += pm[r].x * ki + pm[r].y * kr;
        }
        av[s] = sqrtf(ar * ar + ai * ai);
    }
    float m = fmaxf(fmaxf(av[0], av[1]), fmaxf(av[2], av[3]));
    float e0 = expf(av[0] - m), e1 = expf(av[1] - m), e2 = expf(av[2] - m), e3 = expf(av[3] - m);
    float inv = 4.0f / (e0 + e1 + e2 + e3);
    float re = pm[0].x * e0 + pm[1].x * e1 + pm[2].x * e2 + pm[3].x * e3;
    float im = pm[0].y * e0 + pm[1].y * e1 + pm[2].y * e2 + pm[3].y * e3;
    g_p1[(bt * F1 + 4 * f) * CI + c] = make_float2(re * inv, im * inv);
}

// ================= complex BN stats per (head,b) =================
__global__ void k_stats(const float* __restrict__ gam, const float* __restrict__ bet) {
    int head = blockIdx.x >> 6, b = blockIdx.x & 63;
    const float2* p;
    int N;
    if (head == 0) { p = g_p0 + b * (T0 * F0 * CI); N = T0 * F0 * CI; }
    else           { p = g_p1 + b * (T1 * F1 * CI); N = T1 * F1 * CI; }
    double sr = 0, si = 0, sq = 0;
    for (int i = threadIdx.x; i < N; i += 256) {
        float2 z = p[i];
        sr += z.x; si += z.y;
        sq += (double)z.x * z.x + (double)z.y * z.y;
    }
    __shared__ double rr[256], ri[256], rq[256];
    int tid = threadIdx.x;
    rr[tid] = sr; ri[tid] = si; rq[tid] = sq;
    __syncthreads();
    for (int off = 128; off > 0; off >>= 1) {
        if (tid < off) { rr[tid] += rr[tid + off]; ri[tid] += ri[tid + off]; rq[tid] += rq[tid + off]; }
        __syncthreads();
    }
    if (tid == 0) {
        double mur = rr[0] / N, mui = ri[0] / N;
        double var = rq[0] / N - mur * mur - mui * mui;
        double istd = rsqrt(var + 1e-5);
        float g = gam[head * BB + b], be = bet[head * BB + b];
        float s = (float)(g * istd);
        g_stats[head * BB + b] = make_float4(s, be - (float)mur * s, -(float)mui * s, 0.f);
    }
}

// ================= head0 fused: BN + einsum + iSTFT-64 + bias/relu =================
// grid: 64 b * 8 groups of 16 frames; fk0 resident in smem
__global__ void k_head0(const float* __restrict__ fk0_r, const float* __restrict__ fk0_i,
                        const float* __restrict__ pbias, float* __restrict__ y) {
    extern __shared__ char smraw[];
    float2* fk  = (float2*)smraw;           // F0*CI*CO = 16896
    float2* sx  = fk + F0 * CI * CO;        // 528
    float2* so  = sx + F0 * CI;             // F0*CO = 1056
    float2* tw  = so + F0 * CO;             // 64
    float*  sfr = (float*)(tw + 64);        // 64*33 padded frame

    int tid = threadIdx.x;
    int b   = blockIdx.x >> 3;
    int grp = blockIdx.x & 7;

    for (int i = tid; i < F0 * CI * CO; i += 256)
        fk[i] = make_float2(fk0_r[i], fk0_i[i]);
    if (tid < 64) {
        float s, c; sincospif(tid * (1.0f / 32.0f), &s, &c);
        tw[tid] = make_float2(c, s);
    }
    float4 st = g_stats[b];

    for (int k = 0; k < 16; k++) {
        int t = grp * 16 + k;
        __syncthreads();
        int fb = (b * T0 + t) * (F0 * CI);
        for (int i = tid; i < F0 * CI; i += 256) {
            float2 z = g_p0[fb + i];
            sx[i] = make_float2(z.x * st.x + st.y, z.y * st.x + st.z);
        }
        __syncthreads();
        // einsum over c: out[f][o]
        for (int idx = tid; idx < F0 * CO; idx += 256) {
            int o = idx & 31, f = idx >> 5;
            const float2* xr = sx + f * CI;
            const float2* kk = fk + f * CI * CO + o;
            float re = 0.f, im = 0.f;
            #pragma unroll
            for (int c = 0; c < CI; c++) {
                float2 xv = xr[c];
                float2 kv = kk[c * CO];
                re += xv.x * kv.x - xv.y * kv.y;
                im += xv.x * kv.y + xv.y * kv.x;
            }
            so[f * CO + o] = make_float2(re, im);
        }
        __syncthreads();
        // iSTFT-64 with j <-> 64-j symmetry
        for (int idx = tid; idx < 33 * CO; idx += 256) {
            int o = idx & 31, jp = idx >> 5;   // 0..32
            float x0  = so[o].x;
            float x32 = so[32 * CO + o].x;
            float base = x0 + ((jp & 1) ? -x32 : x32);
            float Cc = 0.f, Ss = 0.f;
            #pragma unroll
            for (int f = 1; f < 32; f++) {
                float2 w = tw[(f * jp) & 63];
                float2 X = so[f * CO + o];
                Cc += X.x * w.x;
                Ss += X.y * w.y;
            }
            sfr[jp * 33 + o] = (base + 2.f * (Cc - Ss)) * (1.0f / 64.0f);
            if (jp >= 1 && jp <= 31)
                sfr[(64 - jp) * 33 + o] = (base + 2.f * (Cc + Ss)) * (1.0f / 64.0f);
        }
        __syncthreads();
        // coalesced store with n/2 shift + wrap, bias + relu
        for (int i = tid; i < N0 * CO; i += 256) {
            int o = i >> 6, j = i & 63;
            float v = sfr[j * 33 + o];
            int s = (t == 0) ? ((j >= 32) ? (j - 32) : (8160 + j)) : (t * 64 + j - 32);
            y[(b * 64 + o) * LEN + s] = fmaxf(v + pbias[o], 0.f);
        }
    }
}

// ================= head1 einsum: BN + per-f channel mix -> g_out1 =================
// grid: 64 b * 4 groups of 8 frames; fk1 streamed through smem once per block
__global__ void k_head1e(const float* __restrict__ fk1_r, const float* __restrict__ fk1_i) {
    extern __shared__ char smraw[];
    float2* sxbn = (float2*)smraw;           // 8 * F1*CI = 16512
    float2* sfk  = sxbn + 8 * F1 * CI;       // CI*CO = 512

    int tid = threadIdx.x;
    int b   = blockIdx.x >> 2;
    int grp = blockIdx.x & 3;
    float4 st = g_stats[BB + b];

    for (int fr = 0; fr < 8; fr++) {
        int fb = (b * T1 + grp * 8 + fr) * (F1 * CI);
        for (int i = tid; i < F1 * CI; i += 256) {
            float2 z = g_p1[fb + i];
            sxbn[fr * (F1 * CI) + i] = make_float2(z.x * st.x + st.y, z.y * st.x + st.z);
        }
    }
    int frq = tid >> 5, o = tid & 31;
    int obase = (b * T1 + grp * 8 + frq) * F1 * CO + o;
    for (int f = 0; f < F1; f++) {
        __syncthreads();
        for (int i = tid; i < CI * CO; i += 256)
            sfk[i] = make_float2(fk1_r[f * CI * CO + i], fk1_i[f * CI * CO + i]);
        __syncthreads();
        const float2* xr = sxbn + frq * (F1 * CI) + f * CI;
        float re = 0.f, im = 0.f;
        #pragma unroll
        for (int c = 0; c < CI; c++) {
            float2 xv = xr[c];
            float2 kv = sfk[c * CO + o];
            re += xv.x * kv.x - xv.y * kv.y;
            im += xv.x * kv.y + xv.y * kv.x;
        }
        g_out1[obase + f * CO] = make_float2(re, im);
    }
}

// ================= iSTFT-256 + bias/relu, block per (b,t) =================
__global__ void k_istft1(const float* __restrict__ pbias, float* __restrict__ y) {
    extern __shared__ char smraw[];
    float2* sX  = (float2*)smraw;            // F1*CO = 4128
    float2* tw  = sX + F1 * CO;              // 256
    float*  sfr = (float*)(tw + 256);        // 256*33 padded

    int tid = threadIdx.x;
    int b = blockIdx.x >> 5, t = blockIdx.x & 31;
    int fb = (b * T1 + t) * (F1 * CO);
    for (int i = tid; i < F1 * CO; i += 256) sX[i] = g_out1[fb + i];
    if (tid < 256) {
        float s, c; sincospif(tid * (1.0f / 128.0f), &s, &c);
        tw[tid] = make_float2(c, s);
    }
    __syncthreads();
    for (int idx = tid; idx < 129 * CO; idx += 256) {
        int o = idx & 31, jp = idx >> 5;     // 0..128
        float x0 = sX[o].x;
        float xN = sX[128 * CO + o].x;
        float base = x0 + ((jp & 1) ? -xN : xN);
        float Cc = 0.f, Ss = 0.f;
        #pragma unroll 4
        for (int f = 1; f < 128; f++) {
            float2 w = tw[(f * jp) & 255];
            float2 X = sX[f * CO + o];
            Cc += X.x * w.x;
            Ss += X.y * w.y;
        }
        sfr[jp * 33 + o] = (base + 2.f * (Cc - Ss)) * (1.0f / 256.0f);
        if (jp >= 1 && jp <= 127)
            sfr[(256 - jp) * 33 + o] = (base + 2.f * (Cc + Ss)) * (1.0f / 256.0f);
    }
    __syncthreads();
    for (int i = tid; i < N1 * CO; i += 256) {
        int o = i >> 8, j = i & 255;
        float v = sfr[j * 33 + o];
        int s = (t == 0) ? ((j >= 128) ? (j - 128) : (8064 + j)) : (t * 256 + j - 128);
        y[(b * 64 + 32 + o) * LEN + s] = fmaxf(v + pbias[32 + o], 0.f);
    }
}

// ================= launcher =================
extern "C" void kernel_launch(void* const* d_in, const int* in_sizes, int n_in,
                              void* d_out, int out_size) {
    const float* x        = (const float*)d_in[0];
    const float* bn_gamma = (const float*)d_in[1];
    const float* bn_beta  = (const float*)d_in[2];
    const float* mk_r     = (const float*)d_in[3];
    const float* mk_i     = (const float*)d_in[4];
    const float* mb_r     = (const float*)d_in[5];
    const float* mb_i     = (const float*)d_in[6];
    const float* fk0_r    = (const float*)d_in[7];
    const float* fk0_i    = (const float*)d_in[8];
    const float* fk1_r    = (const float*)d_in[9];
    const float* fk1_i    = (const float*)d_in[10];
    const float* pbias    = (const float*)d_in[11];
    float* y = (float*)d_out;

    const int SMEM0 = (F0 * CI * CO + F0 * CI + F0 * CO + 64) * 8 + 64 * 33 * 4;   // 156800
    const int SMEM1 = (8 * F1 * CI + CI * CO) * 8;                                  // 136192
    const int SMEM2 = (F1 * CO + 256) * 8 + 256 * 33 * 4;                           // 68864

    cudaFuncSetAttribute(k_head0,  cudaFuncAttributeMaxDynamicSharedMemorySize, SMEM0);
    cudaFuncSetAttribute(k_head1e, cudaFuncAttributeMaxDynamicSharedMemorySize, SMEM1);
    cudaFuncSetAttribute(k_istft1, cudaFuncAttributeMaxDynamicSharedMemorySize, SMEM2);

    k_stft0 <<<BB * T0, 256>>>(x);
    k_stft1 <<<BB * T1, 256>>>(x);
    k_merge <<<(BB * T1 * F0 * CI) / 256, 256>>>(mk_r, mk_i, mb_r, mb_i);
    k_stats <<<2 * BB, 256>>>(bn_gamma, bn_beta);
    k_head0 <<<BB * 8, 256, SMEM0>>>(fk0_r, fk0_i, pbias, y);
    k_head1e<<<BB * 4, 256, SMEM1>>>(fk1_r, fk1_i);
    k_istft1<<<BB * T1, 256, SMEM2>>>(pbias, y);
}

// round 4
// speedup vs baseline: 1.9075x; 1.9075x over previous
#include <cuda_runtime.h>
#include <math.h>

#define BB   64
#define CI   16
#define LEN  8192
#define N0   64
#define F0   33
#define T0   128
#define N1   256
#define F1   129
#define T1   32
#define CO   32

// -------- scratch (device globals; no runtime allocation) --------
__device__ float2 g_p0[BB * T0 * F0 * CI];   // (b,t,f,c) complex
__device__ float2 g_p1[BB * T1 * F1 * CI];   // (b,t,f1,c) complex (becomes acc1)
__device__ float2 g_out1[BB * T1 * F1 * CO]; // head1 spectrum
__device__ float4 g_stats[2 * BB];           // per (head,b): scale, shift_re, shift_im
__device__ double g_part[3 * 1024];          // stats partials

// ================= STFT n=64 : block per (b,t), symmetry + padded smem =================
__global__ void k_stft0(const float* __restrict__ x) {
    int b = blockIdx.x >> 7;
    int t = blockIdx.x & 127;
    __shared__ float  sx[CI * 65];         // pitch 65 (conflict-free)
    __shared__ float2 suv[CI * 33];        // (u,v); slot s=0 holds (x0, x32)
    __shared__ float2 tw[N0];
    int tid = threadIdx.x;
    if (tid < N0) {
        float s, c; sincospif(tid * (1.0f / 32.0f), &s, &c);
        tw[tid] = make_float2(c, s);
    }
    for (int i = tid; i < CI * N0; i += 256) {
        int c = i >> 6, s = i & 63;
        int src = t * N0 + s - 32;
        if (src < 0) src = -src;
        if (src >= LEN) src = 2 * LEN - 2 - src;
        sx[c * 65 + s] = x[(b * CI + c) * LEN + src];
    }
    __syncthreads();
    for (int i = tid; i < CI * 32; i += 256) {
        int c = i >> 5, s = i & 31;
        if (s == 0) {
            suv[c * 33] = make_float2(sx[c * 65], sx[c * 65 + 32]);
        } else {
            float a = sx[c * 65 + s];
            float d = sx[c * 65 + 64 - s];
            suv[c * 33 + s] = make_float2(a + d, a - d);
        }
    }
    __syncthreads();
    int frame = (b * T0 + t) * (F0 * CI);
    for (int idx = tid; idx < F0 * CI; idx += 256) {
        int f = idx >> 4, c = idx & 15;
        const float2* uv = suv + c * 33;
        float re = 0.f, im = 0.f;
        #pragma unroll 8
        for (int s = 1; s < 32; s++) {
            float2 w = tw[(f * s) & 63];
            float2 z = uv[s];
            re += z.x * w.x;
            im -= z.y * w.y;
        }
        float2 e = uv[0];
        re += e.x + ((f & 1) ? -e.y : e.y);
        g_p0[frame + idx] = make_float2(re, im);
    }
}

// ================= STFT n=256 : block per (b,t), symmetry + 2c x 2f tiling =================
__global__ void k_stft1(const float* __restrict__ x) {
    int b = blockIdx.x >> 5;
    int t = blockIdx.x & 31;
    __shared__ float  sx[CI * N1];       // 16 KB
    __shared__ float2 suv[CI * 129];     // (u,v) pitch 129; slot 0 = (x0, x128)
    __shared__ float2 tw[N1];
    int tid = threadIdx.x;
    if (tid < N1) {
        float s, c; sincospif(tid * (1.0f / 128.0f), &s, &c);
        tw[tid] = make_float2(c, s);
    }
    for (int i = tid; i < CI * N1; i += 256) {
        int c = i >> 8, s = i & 255;
        int src = t * N1 + s - 128;
        if (src < 0) src = -src;
        if (src >= LEN) src = 2 * LEN - 2 - src;
        sx[i] = x[(b * CI + c) * LEN + src];
    }
    __syncthreads();
    for (int i = tid; i < CI * 128; i += 256) {
        int c = i >> 7, s = i & 127;
        if (s == 0) {
            suv[c * 129] = make_float2(sx[c << 8], sx[(c << 8) + 128]);
        } else {
            float a = sx[(c << 8) + s];
            float d = sx[(c << 8) + 256 - s];
            suv[c * 129 + s] = make_float2(a + d, a - d);
        }
    }
    __syncthreads();
    int frame = (b * T1 + t) * (F1 * CI);
    // main: 512 items = 64 j x 8 c-pairs; thread handles 2 items
    #pragma unroll
    for (int rep = 0; rep < 2; rep++) {
        int item = tid + rep * 256;
        int j  = item >> 3;          // f pair (j, j+64)
        int c0 = (item & 7) * 2;     // channels c0, c0+1
        const float2* uvA = suv + c0 * 129;
        const float2* uvB = uvA + 129;
        float re00 = 0.f, im00 = 0.f, re01 = 0.f, im01 = 0.f;
        float re10 = 0.f, im10 = 0.f, re11 = 0.f, im11 = 0.f;
        int j2 = j + 64;
        #pragma unroll 4
        for (int s = 1; s < 128; s++) {
            float2 a = uvA[s];
            float2 d = uvB[s];
            float2 w1 = tw[(j * s) & 255];
            float2 w2 = tw[(j2 * s) & 255];
            re00 += a.x * w1.x; im00 -= a.y * w1.y;
            re01 += d.x * w1.x; im01 -= d.y * w1.y;
            re10 += a.x * w2.x; im10 -= a.y * w2.y;
            re11 += d.x * w2.x; im11 -= d.y * w2.y;
        }
        float2 eA = uvA[0], eB = uvB[0];
        float sg1 = (j & 1) ? -1.f : 1.f;   // (-1)^f for f=j; f=j+64 same parity
        re00 += eA.x + sg1 * eA.y;  re01 += eB.x + sg1 * eB.y;
        re10 += eA.x + sg1 * eA.y;  re11 += eB.x + sg1 * eB.y;
        g_p1[frame + j  * CI + c0    ] = make_float2(re00, im00);
        g_p1[frame + j  * CI + c0 + 1] = make_float2(re01, im01);
        g_p1[frame + j2 * CI + c0    ] = make_float2(re10, im10);
        g_p1[frame + j2 * CI + c0 + 1] = make_float2(re11, im11);
    }
    // f = 128: im = 0, cos(pi*s) = (-1)^s
    if (tid < CI) {
        int c = tid;
        const float2* uv = suv + c * 129;
        float re = 0.f;
        #pragma unroll 4
        for (int s = 1; s < 128; s++) {
            float u = uv[s].x;
            re += (s & 1) ? -u : u;
        }
        float2 e = uv[0];
        re += e.x + e.y;  // f=128 even
        g_p1[frame + 128 * CI + c] = make_float2(re, 0.f);
    }
}

// ================= attention merge : writes directly into p1 (acc1) =================
__global__ void k_merge(const float* __restrict__ mk_r, const float* __restrict__ mk_i,
                        const float* __restrict__ mb_r, const float* __restrict__ mb_i) {
    __shared__ float skr[16], ski[16], sbr[4], sbi[4];
    int tid = threadIdx.x;
    if (tid < 16) { skr[tid] = mk_r[tid]; ski[tid] = mk_i[tid]; }
    if (tid < 4)  { sbr[tid] = mb_r[tid]; sbi[tid] = mb_i[tid]; }
    __syncthreads();
    int g = blockIdx.x * 256 + tid;
    if (g >= BB * T1 * F0 * CI) return;
    int c  = g & 15;
    int f  = (g >> 4) % F0;
    int bt = (g >> 4) / F0;          // b*32 + t

    int base = ((((bt >> 5) * T0) + 4 * (bt & 31)) * F0 + f) * CI + c;
    float2 pm[4];
    #pragma unroll
    for (int r = 0; r < 4; r++) pm[r] = g_p0[base + r * (F0 * CI)];

    float av[4];
    #pragma unroll
    for (int s = 0; s < 4; s++) {
        float ar = sbr[s], ai = sbi[s];
        #pragma unroll
        for (int r = 0; r < 4; r++) {
            float kr = skr[r * 4 + s], ki = ski[r * 4 + s];
            ar += pm[r].x * kr - pm[r].y * ki;
            ai += pm[r].x * ki + pm[r].y * kr;
        }
        av[s] = sqrtf(ar * ar + ai * ai);
    }
    float m = fmaxf(fmaxf(av[0], av[1]), fmaxf(av[2], av[3]));
    float e0 = expf(av[0] - m), e1 = expf(av[1] - m), e2 = expf(av[2] - m), e3 = expf(av[3] - m);
    float inv = 4.0f / (e0 + e1 + e2 + e3);
    float re = pm[0].x * e0 + pm[1].x * e1 + pm[2].x * e2 + pm[3].x * e3;
    float im = pm[0].y * e0 + pm[1].y * e1 + pm[2].y * e2 + pm[3].y * e3;
    g_p1[(bt * F1 + 4 * f) * CI + c] = make_float2(re * inv, im * inv);
}

// ================= BN stats: two-stage parallel reduction =================
__global__ void k_stats_part() {
    int head  = blockIdx.x >> 9;
    int b     = (blockIdx.x >> 3) & 63;
    int chunk = blockIdx.x & 7;
    const float4* p;
    int per;   // float4 per chunk
    if (head == 0) { p = (const float4*)(g_p0 + b * (T0 * F0 * CI)); per = (T0 * F0 * CI) / 16; }
    else           { p = (const float4*)(g_p1 + b * (T1 * F1 * CI)); per = (T1 * F1 * CI) / 16; }
    double sr = 0, si = 0, sq = 0;
    int end = (chunk + 1) * per;
    for (int i = chunk * per + threadIdx.x; i < end; i += 256) {
        float4 z = p[i];
        sr += (double)z.x + (double)z.z;
        si += (double)z.y + (double)z.w;
        sq += (double)z.x * z.x + (double)z.y * z.y + (double)z.z * z.z + (double)z.w * z.w;
    }
    __shared__ double rr[256], ri[256], rq[256];
    int tid = threadIdx.x;
    rr[tid] = sr; ri[tid] = si; rq[tid] = sq;
    __syncthreads();
    for (int off = 128; off > 0; off >>= 1) {
        if (tid < off) { rr[tid] += rr[tid + off]; ri[tid] += ri[tid + off]; rq[tid] += rq[tid + off]; }
        __syncthreads();
    }
    if (tid == 0) {
        g_part[blockIdx.x]        = rr[0];
        g_part[1024 + blockIdx.x] = ri[0];
        g_part[2048 + blockIdx.x] = rq[0];
    }
}

__global__ void k_stats_fin(const float* __restrict__ gam, const float* __restrict__ bet) {
    int i = threadIdx.x;          // 0..127: head = i>>6, b = i&63
    if (i >= 128) return;
    double sr = 0, si = 0, sq = 0;
    int base = i * 8;
    #pragma unroll
    for (int c = 0; c < 8; c++) {
        sr += g_part[base + c];
        si += g_part[1024 + base + c];
        sq += g_part[2048 + base + c];
    }
    int head = i >> 6, b = i & 63;
    int N = head ? (T1 * F1 * CI) : (T0 * F0 * CI);
    double mur = sr / N, mui = si / N;
    double var = sq / N - mur * mur - mui * mui;
    double istd = rsqrt(var + 1e-5);
    float g = gam[head * BB + b], be = bet[head * BB + b];
    float s = (float)(g * istd);
    g_stats[i] = make_float4(s, be - (float)mur * s, -(float)mui * s, 0.f);
}

// ================= head0 fused: BN + einsum + iSTFT-64 + bias/relu =================
__global__ void k_head0(const float* __restrict__ fk0_r, const float* __restrict__ fk0_i,
                        const float* __restrict__ pbias, float* __restrict__ y) {
    extern __shared__ char smraw[];
    float2* fk  = (float2*)smraw;           // F0*CI*CO
    float2* sx  = fk + F0 * CI * CO;
    float2* so  = sx + F0 * CI;
    float2* tw  = so + F0 * CO;
    float*  sfr = (float*)(tw + 64);

    int tid = threadIdx.x;
    int b   = blockIdx.x >> 3;
    int grp = blockIdx.x & 7;

    for (int i = tid; i < F0 * CI * CO; i += 256)
        fk[i] = make_float2(fk0_r[i], fk0_i[i]);
    if (tid < 64) {
        float s, c; sincospif(tid * (1.0f / 32.0f), &s, &c);
        tw[tid] = make_float2(c, s);
    }
    float4 st = g_stats[b];

    for (int k = 0; k < 16; k++) {
        int t = grp * 16 + k;
        __syncthreads();
        int fb = (b * T0 + t) * (F0 * CI);
        for (int i = tid; i < F0 * CI; i += 256) {
            float2 z = g_p0[fb + i];
            sx[i] = make_float2(z.x * st.x + st.y, z.y * st.x + st.z);
        }
        __syncthreads();
        for (int idx = tid; idx < F0 * CO; idx += 256) {
            int o = idx & 31, f = idx >> 5;
            const float2* xr = sx + f * CI;
            const float2* kk = fk + f * CI * CO + o;
            float re = 0.f, im = 0.f;
            #pragma unroll
            for (int c = 0; c < CI; c++) {
                float2 xv = xr[c];
                float2 kv = kk[c * CO];
                re += xv.x * kv.x - xv.y * kv.y;
                im += xv.x * kv.y + xv.y * kv.x;
            }
            so[f * CO + o] = make_float2(re, im);
        }
        __syncthreads();
        for (int idx = tid; idx < 33 * CO; idx += 256) {
            int o = idx & 31, jp = idx >> 5;
            float x0  = so[o].x;
            float x32 = so[32 * CO + o].x;
            float base = x0 + ((jp & 1) ? -x32 : x32);
            float Cc = 0.f, Ss = 0.f;
            #pragma unroll
            for (int f = 1; f < 32; f++) {
                float2 w = tw[(f * jp) & 63];
                float2 X = so[f * CO + o];
                Cc += X.x * w.x;
                Ss += X.y * w.y;
            }
            sfr[jp * 33 + o] = (base + 2.f * (Cc - Ss)) * (1.0f / 64.0f);
            if (jp >= 1 && jp <= 31)
                sfr[(64 - jp) * 33 + o] = (base + 2.f * (Cc + Ss)) * (1.0f / 64.0f);
        }
        __syncthreads();
        for (int i = tid; i < N0 * CO; i += 256) {
            int o = i >> 6, j = i & 63;
            float v = sfr[j * 33 + o];
            int s = (t == 0) ? ((j >= 32) ? (j - 32) : (8160 + j)) : (t * 64 + j - 32);
            y[(b * 64 + o) * LEN + s] = fmaxf(v + pbias[o], 0.f);
        }
    }
}

// ================= head1 einsum, f-major: block per (f, bt-chunk) =================
__global__ void k_head1e(const float* __restrict__ fk1_r, const float* __restrict__ fk1_i) {
    __shared__ float2 sfk[CI * CO];     // fk1[f]
    __shared__ float2 sxb[32 * CI];     // staging: 32 bt x 16 c (BN applied)
    int tid   = threadIdx.x;
    int chunk = blockIdx.x & 3;
    int f     = blockIdx.x >> 2;

    for (int i = tid; i < CI * CO; i += 256)
        sfk[i] = make_float2(fk1_r[f * CI * CO + i], fk1_i[f * CI * CO + i]);

    int wid = tid >> 5, o = tid & 31;
    for (int iter = 0; iter < 16; iter++) {
        int bt0 = chunk * 512 + iter * 32;
        __syncthreads();
        #pragma unroll
        for (int r = 0; r < 2; r++) {
            int idx = tid + r * 256;            // 0..511
            int bti = idx >> 4, c = idx & 15;
            int bt  = bt0 + bti;
            float4 st = g_stats[BB + (bt >> 5)];
            float2 z  = g_p1[(bt * F1 + f) * CI + c];
            sxb[idx] = make_float2(z.x * st.x + st.y, z.y * st.x + st.z);
        }
        __syncthreads();
        #pragma unroll
        for (int sub = 0; sub < 4; sub++) {
            int bti = wid * 4 + sub;
            const float2* xr = sxb + bti * CI;
            float re = 0.f, im = 0.f;
            #pragma unroll
            for (int c = 0; c < CI; c++) {
                float2 xv = xr[c];
                float2 kv = sfk[c * CO + o];
                re += xv.x * kv.x - xv.y * kv.y;
                im += xv.x * kv.y + xv.y * kv.x;
            }
            g_out1[((bt0 + bti) * F1 + f) * CO + o] = make_float2(re, im);
        }
    }
}

// ================= iSTFT-256 + bias/relu, 2x2 register tiling =================
__global__ void k_istft1(const float* __restrict__ pbias, float* __restrict__ y) {
    extern __shared__ char smraw[];
    float2* sX  = (float2*)smraw;            // F1*CO
    float2* tw  = sX + F1 * CO;              // 256
    float*  sfr = (float*)(tw + 256);        // 256*33 padded

    int tid = threadIdx.x;
    int b = blockIdx.x >> 5, t = blockIdx.x & 31;
    int fb = (b * T1 + t) * (F1 * CO);
    for (int i = tid; i < F1 * CO; i += 256) sX[i] = g_out1[fb + i];
    {
        float s, c; sincospif(tid * (1.0f / 128.0f), &s, &c);
        tw[tid] = make_float2(c, s);
    }
    __syncthreads();
    const float inv = 1.0f / 256.0f;
    // main tiles: 1024 = 64 u x 16 o0; 4 per thread. jp pair (2u, 2u+1), o pair (o0, o0+16)
    #pragma unroll
    for (int rep = 0; rep < 4; rep++) {
        int tile = tid + rep * 256;
        int u  = tile >> 4;
        int o0 = tile & 15;
        int jp0 = 2 * u, jp1 = 2 * u + 1;
        float Cc00 = 0.f, Ss00 = 0.f, Cc01 = 0.f, Ss01 = 0.f;
        float Cc10 = 0.f, Ss10 = 0.f, Cc11 = 0.f, Ss11 = 0.f;
        #pragma unroll 4
        for (int f = 1; f < 128; f++) {
            float2 X0 = sX[f * CO + o0];
            float2 X1 = sX[f * CO + o0 + 16];
            float2 w0 = tw[(f * jp0) & 255];
            float2 w1 = tw[(f * jp1) & 255];
            Cc00 += X0.x * w0.x; Ss00 += X0.y * w0.y;
            Cc01 += X1.x * w0.x; Ss01 += X1.y * w0.y;
            Cc10 += X0.x * w1.x; Ss10 += X0.y * w1.y;
            Cc11 += X1.x * w1.x; Ss11 += X1.y * w1.y;
        }
        float x0a = sX[o0].x,        xNa = sX[128 * CO + o0].x;
        float x0b = sX[o0 + 16].x,   xNb = sX[128 * CO + o0 + 16].x;
        // jp0 = 2u (even): base = x0 + xN
        {
            float ba = x0a + xNa, bb = x0b + xNb;
            sfr[jp0 * 33 + o0]      = (ba + 2.f * (Cc00 - Ss00)) * inv;
            sfr[jp0 * 33 + o0 + 16] = (bb + 2.f * (Cc01 - Ss01)) * inv;
            if (jp0 >= 1) {
                sfr[(256 - jp0) * 33 + o0]      = (ba + 2.f * (Cc00 + Ss00)) * inv;
                sfr[(256 - jp0) * 33 + o0 + 16] = (bb + 2.f * (Cc01 + Ss01)) * inv;
            }
        }
        // jp1 = 2u+1 (odd): base = x0 - xN
        {
            float ba = x0a - xNa, bb = x0b - xNb;
            sfr[jp1 * 33 + o0]      = (ba + 2.f * (Cc10 - Ss10)) * inv;
            sfr[jp1 * 33 + o0 + 16] = (bb + 2.f * (Cc11 - Ss11)) * inv;
            sfr[(256 - jp1) * 33 + o0]      = (ba + 2.f * (Cc10 + Ss10)) * inv;
            sfr[(256 - jp1) * 33 + o0 + 16] = (bb + 2.f * (Cc11 + Ss11)) * inv;
        }
    }
    // jp = 128 leftover: sin terms vanish, cos(pi f) = (-1)^f
    if (tid < 32) {
        int o = tid;
        float acc = 0.f;
        #pragma unroll 4
        for (int f = 1; f < 128; f++) {
            float v = sX[f * CO + o].x;
            acc += (f & 1) ? -v : v;
        }
        float base = sX[o].x + sX[128 * CO + o].x;
        sfr[128 * 33 + o] = (base + 2.f * acc) * inv;
    }
    __syncthreads();
    for (int i = tid; i < N1 * CO; i += 256) {
        int o = i >> 8, j = i & 255;
        float v = sfr[j * 33 + o];
        int s = (t == 0) ? ((j >= 128) ? (j - 128) : (8064 + j)) : (t * 256 + j - 128);
        y[(b * 64 + 32 + o) * LEN + s] = fmaxf(v + pbias[32 + o], 0.f);
    }
}

// ================= launcher =================
extern "C" void kernel_launch(void* const* d_in, const int* in_sizes, int n_in,
                              void* d_out, int out_size) {
    const float* x        = (const float*)d_in[0];
    const float* bn_gamma = (const float*)d_in[1];
    const float* bn_beta  = (const float*)d_in[2];
    const float* mk_r     = (const float*)d_in[3];
    const float* mk_i     = (const float*)d_in[4];
    const float* mb_r     = (const float*)d_in[5];
    const float* mb_i     = (const float*)d_in[6];
    const float* fk0_r    = (const float*)d_in[7];
    const float* fk0_i    = (const float*)d_in[8];
    const float* fk1_r    = (const float*)d_in[9];
    const float* fk1_i    = (const float*)d_in[10];
    const float* pbias    = (const float*)d_in[11];
    float* y = (float*)d_out;

    const int SMEM0 = (F0 * CI * CO + F0 * CI + F0 * CO + 64) * 8 + 64 * 33 * 4;   // head0
    const int SMEM2 = (F1 * CO + 256) * 8 + 256 * 33 * 4;                           // istft1

    cudaFuncSetAttribute(k_head0,  cudaFuncAttributeMaxDynamicSharedMemorySize, SMEM0);
    cudaFuncSetAttribute(k_istft1, cudaFuncAttributeMaxDynamicSharedMemorySize, SMEM2);

    k_stft0 <<<BB * T0, 256>>>(x);
    k_stft1 <<<BB * T1, 256>>>(x);
    k_merge <<<(BB * T1 * F0 * CI) / 256, 256>>>(mk_r, mk_i, mb_r, mb_i);
    k_stats_part<<<1024, 256>>>();
    k_stats_fin <<<1, 128>>>(bn_gamma, bn_beta);
    k_head0 <<<BB * 8, 256, SMEM0>>>(fk0_r, fk0_i, pbias, y);
    k_head1e<<<F1 * 4, 256>>>(fk1_r, fk1_i);
    k_istft1<<<BB * T1, 256, SMEM2>>>(pbias, y);
}

// round 6
// speedup vs baseline: 2.8685x; 1.5038x over previous
#include <cuda_runtime.h>
#include <math.h>

#define BB   64
#define CI   16
#define LEN  8192
#define N0   64
#define F0   33
#define T0   128
#define N1   256
#define F1   129
#define T1   32
#define CO   32

// -------- scratch (device globals; no runtime allocation) --------
__device__ float2 g_p0[BB * T0 * F0 * CI];   // (b,t,f,c) complex
__device__ float2 g_p1[BB * T1 * F1 * CI];   // (b,t,f1,c) complex (becomes acc1)
__device__ float2 g_out1[BB * T1 * F1 * CO]; // head1 spectrum
__device__ float4 g_stats[2 * BB];           // per (head,b): scale, shift_re, shift_im
__device__ float  g_partf[3 * 1024];         // stats partials (fp32)

// ================= STFT n=64 : 128 thr, fold symmetry + 2f x 2c tiling =================
__global__ void k_stft0(const float* __restrict__ x) {
    int b = blockIdx.x >> 7;
    int t = blockIdx.x & 127;
    __shared__ float  sx[CI * 65];
    __shared__ float2 suv[CI * 33];      // (u,v); slot 0 = (x0, x32)
    __shared__ float2 tw[N0];
    int tid = threadIdx.x;
    if (tid < N0) {
        float s, c; sincospif(tid * (1.0f / 32.0f), &s, &c);
        tw[tid] = make_float2(c, s);
    }
    for (int i = tid; i < CI * N0; i += 128) {
        int c = i >> 6, s = i & 63;
        int src = t * N0 + s - 32;
        if (src < 0) src = -src;
        if (src >= LEN) src = 2 * LEN - 2 - src;
        sx[c * 65 + s] = x[(b * CI + c) * LEN + src];
    }
    __syncthreads();
    for (int i = tid; i < CI * 32; i += 128) {
        int c = i >> 5, s = i & 31;
        if (s == 0) {
            suv[c * 33] = make_float2(sx[c * 65], sx[c * 65 + 32]);
        } else {
            float a = sx[c * 65 + s];
            float d = sx[c * 65 + 64 - s];
            suv[c * 33 + s] = make_float2(a + d, a - d);
        }
    }
    __syncthreads();
    int frame = (b * T0 + t) * (F0 * CI);
    int u  = tid >> 3;        // f in {u, u+16}
    int cg = tid & 7;         // c in {cg, cg+8}
    float r00 = 0.f, i00 = 0.f, r01 = 0.f, i01 = 0.f;
    float r10 = 0.f, i10 = 0.f, r11 = 0.f, i11 = 0.f;
    int ia = 0, ib = 0;
    #pragma unroll 4
    for (int s = 1; s < 32; s++) {
        ia = (ia + u) & 63;
        ib = (ib + u + 16) & 63;
        float2 a0 = suv[cg * 33 + s];
        float2 a1 = suv[(cg + 8) * 33 + s];
        float2 w0 = tw[ia];
        float2 w1 = tw[ib];
        r00 += a0.x * w0.x; i00 -= a0.y * w0.y;
        r01 += a1.x * w0.x; i01 -= a1.y * w0.y;
        r10 += a0.x * w1.x; i10 -= a0.y * w1.y;
        r11 += a1.x * w1.x; i11 -= a1.y * w1.y;
    }
    float2 e0 = suv[cg * 33];
    float2 e1 = suv[(cg + 8) * 33];
    float sg = (u & 1) ? -1.f : 1.f;      // f=u and u+16 same parity
    float ea = e0.x + sg * e0.y, eb = e1.x + sg * e1.y;
    g_p0[frame + u * CI + cg]            = make_float2(r00 + ea, i00);
    g_p0[frame + u * CI + cg + 8]        = make_float2(r01 + eb, i01);
    g_p0[frame + (u + 16) * CI + cg]     = make_float2(r10 + ea, i10);
    g_p0[frame + (u + 16) * CI + cg + 8] = make_float2(r11 + eb, i11);
    if (tid < 16) {
        const float2* uv = suv + tid * 33;
        float re = 0.f;
        #pragma unroll 4
        for (int s = 1; s < 32; s++) {
            float uu = uv[s].x;
            re += (s & 1) ? -uu : uu;
        }
        float2 e = uv[0];
        g_p0[frame + 32 * CI + tid] = make_float2(re + e.x + e.y, 0.f);
    }
}

// ===== STFT n=256 : 128 thr, fold + parity split (f & 128-f) + 4f x 2c tiling =====
__global__ void k_stft1(const float* __restrict__ x) {
    int b = blockIdx.x >> 5;
    int t = blockIdx.x & 31;
    __shared__ float  sx[CI * N1];
    __shared__ float2 suv[CI * 129];     // (u,v); slot 0 = (x0, x128)
    __shared__ float2 tw[N1];
    int tid = threadIdx.x;
    for (int i = tid; i < N1; i += 128) {
        float s, c; sincospif(i * (1.0f / 128.0f), &s, &c);
        tw[i] = make_float2(c, s);
    }
    for (int i = tid; i < CI * N1; i += 128) {
        int c = i >> 8, s = i & 255;
        int src = t * N1 + s - 128;
        if (src < 0) src = -src;
        if (src >= LEN) src = 2 * LEN - 2 - src;
        sx[i] = x[(b * CI + c) * LEN + src];
    }
    __syncthreads();
    for (int i = tid; i < CI * 128; i += 128) {
        int c = i >> 7, s = i & 127;
        if (s == 0) {
            suv[c * 129] = make_float2(sx[c << 8], sx[(c << 8) + 128]);
        } else {
            float a = sx[(c << 8) + s];
            float d = sx[(c << 8) + 256 - s];
            suv[c * 129 + s] = make_float2(a + d, a - d);
        }
    }
    __syncthreads();
    int frame = (b * T1 + t) * (F1 * CI);
    int u  = tid >> 3;        // f = u + 16k, k=0..3 (f in 0..63; mirrors 65..128)
    int cg = tid & 7;         // c in {cg, cg+8}
    float Ce[4][2], Co[4][2], Se[4][2], So[4][2];
    int io[4], ie[4], fq[4];
    #pragma unroll
    for (int k = 0; k < 4; k++) {
        fq[k] = u + 16 * k;
        io[k] = fq[k];        // f * 1
        ie[k] = 0;
        #pragma unroll
        for (int m = 0; m < 2; m++) { Ce[k][m] = Co[k][m] = Se[k][m] = So[k][m] = 0.f; }
    }
    const float2* uvA = suv + cg * 129;
    const float2* uvB = uvA + 8 * 129;
    // h = 0 : s = 1 (odd only)
    {
        float2 a0 = uvA[1], a1 = uvB[1];
        #pragma unroll
        for (int k = 0; k < 4; k++) {
            float2 w = tw[io[k]];
            Co[k][0] += a0.x * w.x;  So[k][0] += a0.y * w.y;
            Co[k][1] += a1.x * w.x;  So[k][1] += a1.y * w.y;
        }
    }
    #pragma unroll 2
    for (int h = 1; h < 64; h++) {
        int se = 2 * h, so = 2 * h + 1;
        float2 e0 = uvA[se], e1 = uvB[se];
        float2 o0 = uvA[so], o1 = uvB[so];
        #pragma unroll
        for (int k = 0; k < 4; k++) {
            ie[k] = (ie[k] + 2 * fq[k]) & 255;
            io[k] = (io[k] + 2 * fq[k]) & 255;
            float2 we = tw[ie[k]];
            float2 wo = tw[io[k]];
            Ce[k][0] += e0.x * we.x;  Se[k][0] += e0.y * we.y;
            Ce[k][1] += e1.x * we.x;  Se[k][1] += e1.y * we.y;
            Co[k][0] += o0.x * wo.x;  So[k][0] += o0.y * wo.y;
            Co[k][1] += o1.x * wo.x;  So[k][1] += o1.y * wo.y;
        }
    }
    float2 eA = uvA[0], eB = uvB[0];
    float sg = (u & 1) ? -1.f : 1.f;     // parity(f) = parity(u) for all k
    float ea = eA.x + sg * eA.y, eb = eB.x + sg * eB.y;
    #pragma unroll
    for (int k = 0; k < 4; k++) {
        int f = fq[k];
        // c = cg
        g_p1[frame + f * CI + cg]          = make_float2(ea + Ce[k][0] + Co[k][0], -(Se[k][0] + So[k][0]));
        g_p1[frame + (128 - f) * CI + cg]  = make_float2(ea + Ce[k][0] - Co[k][0],   Se[k][0] - So[k][0]);
        // c = cg + 8
        g_p1[frame + f * CI + cg + 8]         = make_float2(eb + Ce[k][1] + Co[k][1], -(Se[k][1] + So[k][1]));
        g_p1[frame + (128 - f) * CI + cg + 8] = make_float2(eb + Ce[k][1] - Co[k][1],   Se[k][1] - So[k][1]);
    }
    // f = 64 special: cos = (-1)^g on even s, sin = (-1)^g on odd s
    if (tid < 16) {
        const float2* uv = suv + tid * 129;
        float re = 0.f, im = 0.f;
        #pragma unroll 4
        for (int g = 1; g < 64; g++) {
            float uu = uv[2 * g].x;
            re += (g & 1) ? -uu : uu;
        }
        #pragma unroll 4
        for (int g = 0; g < 64; g++) {
            float vv = uv[2 * g + 1].y;
            im += (g & 1) ? vv : -vv;     // im = -sum (-1)^g v
        }
        float2 e = uv[0];
        g_p1[frame + 64 * CI + tid] = make_float2(re + e.x + e.y, im);
    }
}

// ================= attention merge : writes directly into p1 (acc1) =================
__global__ void k_merge(const float* __restrict__ mk_r, const float* __restrict__ mk_i,
                        const float* __restrict__ mb_r, const float* __restrict__ mb_i) {
    __shared__ float skr[16], ski[16], sbr[4], sbi[4];
    int tid = threadIdx.x;
    if (tid < 16) { skr[tid] = mk_r[tid]; ski[tid] = mk_i[tid]; }
    if (tid < 4)  { sbr[tid] = mb_r[tid]; sbi[tid] = mb_i[tid]; }
    __syncthreads();
    int g = blockIdx.x * 256 + tid;
    if (g >= BB * T1 * F0 * CI) return;
    int c  = g & 15;
    int f  = (g >> 4) % F0;
    int bt = (g >> 4) / F0;          // b*32 + t

    int base = ((((bt >> 5) * T0) + 4 * (bt & 31)) * F0 + f) * CI + c;
    float2 pm[4];
    #pragma unroll
    for (int r = 0; r < 4; r++) pm[r] = g_p0[base + r * (F0 * CI)];

    float av[4];
    #pragma unroll
    for (int s = 0; s < 4; s++) {
        float ar = sbr[s], ai = sbi[s];
        #pragma unroll
        for (int r = 0; r < 4; r++) {
            float kr = skr[r * 4 + s], ki = ski[r * 4 + s];
            ar += pm[r].x * kr - pm[r].y * ki;
            ai += pm[r].x * ki + pm[r].y * kr;
        }
        av[s] = sqrtf(ar * ar + ai * ai);
    }
    float m = fmaxf(fmaxf(av[0], av[1]), fmaxf(av[2], av[3]));
    float e0 = expf(av[0] - m), e1 = expf(av[1] - m), e2 = expf(av[2] - m), e3 = expf(av[3] - m);
    float inv = 4.0f / (e0 + e1 + e2 + e3);
    float re = pm[0].x * e0 + pm[1].x * e1 + pm[2].x * e2 + pm[3].x * e3;
    float im = pm[0].y * e0 + pm[1].y * e1 + pm[2].y * e2 + pm[3].y * e3;
    g_p1[(bt * F1 + 4 * f) * CI + c] = make_float2(re * inv, im * inv);
}

// ================= BN stats: fp32 partials, two-stage =================
__global__ void k_stats_part() {
    int head  = blockIdx.x >> 9;
    int b     = (blockIdx.x >> 3) & 63;
    int chunk = blockIdx.x & 7;
    const float4* p;
    int per;
    if (head == 0) { p = (const float4*)(g_p0 + b * (T0 * F0 * CI)); per = (T0 * F0 * CI) / 16; }
    else           { p = (const float4*)(g_p1 + b * (T1 * F1 * CI)); per = (T1 * F1 * CI) / 16; }
    float sr = 0.f, si = 0.f, sq = 0.f;
    int base = chunk * per, end = base + per;
    #pragma unroll 4
    for (int i = base + threadIdx.x; i < end; i += 256) {
        float4 z = p[i];
        sr += z.x + z.z;
        si += z.y + z.w;
        sq += z.x * z.x + z.y * z.y + z.z * z.z + z.w * z.w;
    }
    #pragma unroll
    for (int off = 16; off; off >>= 1) {
        sr += __shfl_xor_sync(0xffffffffu, sr, off);
        si += __shfl_xor_sync(0xffffffffu, si, off);
        sq += __shfl_xor_sync(0xffffffffu, sq, off);
    }
    __shared__ float wr[8], wi[8], wq[8];
    int tid = threadIdx.x;
    if ((tid & 31) == 0) { wr[tid >> 5] = sr; wi[tid >> 5] = si; wq[tid >> 5] = sq; }
    __syncthreads();
    if (tid == 0) {
        float a = 0.f, bb2 = 0.f, c = 0.f;
        #pragma unroll
        for (int w = 0; w < 8; w++) { a += wr[w]; bb2 += wi[w]; c += wq[w]; }
        g_partf[blockIdx.x]        = a;
        g_partf[1024 + blockIdx.x] = bb2;
        g_partf[2048 + blockIdx.x] = c;
    }
}

__global__ void k_stats_fin(const float* __restrict__ gam, const float* __restrict__ bet) {
    int i = threadIdx.x;
    if (i >= 128) return;
    double sr = 0, si = 0, sq = 0;
    int base = i * 8;
    #pragma unroll
    for (int c = 0; c < 8; c++) {
        sr += (double)g_partf[base + c];
        si += (double)g_partf[1024 + base + c];
        sq += (double)g_partf[2048 + base + c];
    }
    int head = i >> 6, b = i & 63;
    int N = head ? (T1 * F1 * CI) : (T0 * F0 * CI);
    double mur = sr / N, mui = si / N;
    double var = sq / N - mur * mur - mui * mui;
    double istd = rsqrt(var + 1e-5);
    float g = gam[head * BB + b], be = bet[head * BB + b];
    float s = (float)(g * istd);
    g_stats[i] = make_float4(s, be - (float)mur * s, -(float)mui * s, 0.f);
}

// ================= head0 fused: BN + einsum + iSTFT-64 (2j x 2o) + bias/relu =================
__global__ void k_head0(const float* __restrict__ fk0_r, const float* __restrict__ fk0_i,
                        const float* __restrict__ pbias, float* __restrict__ y) {
    extern __shared__ char smraw[];
    float2* fk  = (float2*)smraw;           // F0*CI*CO
    float2* sx  = fk + F0 * CI * CO;
    float2* so  = sx + F0 * CI;
    float2* tw  = so + F0 * CO;
    float*  sfr = (float*)(tw + 64);

    int tid = threadIdx.x;
    int b   = blockIdx.x >> 3;
    int grp = blockIdx.x & 7;

    for (int i = tid; i < F0 * CI * CO; i += 256)
        fk[i] = make_float2(fk0_r[i], fk0_i[i]);
    if (tid < 64) {
        float s, c; sincospif(tid * (1.0f / 32.0f), &s, &c);
        tw[tid] = make_float2(c, s);
    }
    float4 st = g_stats[b];
    const float inv = 1.0f / 64.0f;

    for (int k = 0; k < 16; k++) {
        int t = grp * 16 + k;
        __syncthreads();
        int fb = (b * T0 + t) * (F0 * CI);
        for (int i = tid; i < F0 * CI; i += 256) {
            float2 z = g_p0[fb + i];
            sx[i] = make_float2(z.x * st.x + st.y, z.y * st.x + st.z);
        }
        __syncthreads();
        for (int idx = tid; idx < F0 * CO; idx += 256) {
            int o = idx & 31, f = idx >> 5;
            const float2* xr = sx + f * CI;
            const float2* kk = fk + f * CI * CO + o;
            float re = 0.f, im = 0.f;
            #pragma unroll
            for (int c = 0; c < CI; c++) {
                float2 xv = xr[c];
                float2 kv = kk[c * CO];
                re += xv.x * kv.x - xv.y * kv.y;
                im += xv.x * kv.y + xv.y * kv.x;
            }
            so[f * CO + o] = make_float2(re, im);
        }
        __syncthreads();
        // iSTFT-64, 2j x 2o register tile
        {
            int u  = tid >> 4;       // jp in {u, u+16}
            int o0 = tid & 15;       // o in {o0, o0+16}
            float c00 = 0.f, s00 = 0.f, c01 = 0.f, s01 = 0.f;
            float c10 = 0.f, s10 = 0.f, c11 = 0.f, s11 = 0.f;
            int ia = 0, ib = 0;
            #pragma unroll 4
            for (int f = 1; f < 32; f++) {
                ia = (ia + u) & 63;
                ib = (ib + u + 16) & 63;
                float2 X0 = so[f * CO + o0];
                float2 X1 = so[f * CO + o0 + 16];
                float2 w0 = tw[ia];
                float2 w1 = tw[ib];
                c00 += X0.x * w0.x; s00 += X0.y * w0.y;
                c01 += X1.x * w0.x; s01 += X1.y * w0.y;
                c10 += X0.x * w1.x; s10 += X0.y * w1.y;
                c11 += X1.x * w1.x; s11 += X1.y * w1.y;
            }
            float x0a = so[o0].x,      xNa = so[32 * CO + o0].x;
            float x0b = so[o0 + 16].x, xNb = so[32 * CO + o0 + 16].x;
            float sg = (u & 1) ? -1.f : 1.f;      // jp=u and u+16 same parity
            float bA = x0a + sg * xNa, bB = x0b + sg * xNb;
            int jp0 = u, jp1 = u + 16;
            sfr[jp0 * 33 + o0]      = (bA + 2.f * (c00 - s00)) * inv;
            sfr[jp0 * 33 + o0 + 16] = (bB + 2.f * (c01 - s01)) * inv;
            if (jp0 >= 1) {
                sfr[(64 - jp0) * 33 + o0]      = (bA + 2.f * (c00 + s00)) * inv;
                sfr[(64 - jp0) * 33 + o0 + 16] = (bB + 2.f * (c01 + s01)) * inv;
            }
            sfr[jp1 * 33 + o0]      = (bA + 2.f * (c10 - s10)) * inv;
            sfr[jp1 * 33 + o0 + 16] = (bB + 2.f * (c11 - s11)) * inv;
            sfr[(64 - jp1) * 33 + o0]      = (bA + 2.f * (c10 + s10)) * inv;
            sfr[(64 - jp1) * 33 + o0 + 16] = (bB + 2.f * (c11 + s11)) * inv;
        }
        if (tid < 32) {          // jp = 32
            int o = tid;
            float acc = 0.f;
            #pragma unroll 4
            for (int f = 1; f < 32; f++) {
                float v = so[f * CO + o].x;
                acc += (f & 1) ? -v : v;
            }
            float bs = so[o].x + so[32 * CO + o].x;
            sfr[32 * 33 + o] = (bs + 2.f * acc) * inv;
        }
        __syncthreads();
        for (int i = tid; i < N0 * CO; i += 256) {
            int o = i >> 6, j = i & 63;
            float v = sfr[j * 33 + o];
            int s = (t == 0) ? ((j >= 32) ? (j - 32) : (8160 + j)) : (t * 64 + j - 32);
            y[(b * 64 + o) * LEN + s] = fmaxf(v + pbias[o], 0.f);
        }
    }
}

// ================= head1 einsum, f-major, 2bt x 2o register tile =================
__global__ void k_head1e(const float* __restrict__ fk1_r, const float* __restrict__ fk1_i) {
    __shared__ float2 sfk[CI * CO];     // fk1[f]
    __shared__ float2 sxb[32 * CI];     // staging: 32 bt x 16 c (BN applied)
    int tid   = threadIdx.x;
    int chunk = blockIdx.x & 3;
    int f     = blockIdx.x >> 2;

    for (int i = tid; i < CI * CO; i += 256)
        sfk[i] = make_float2(fk1_r[f * CI * CO + i], fk1_i[f * CI * CO + i]);

    int wid = tid >> 5, lane = tid & 31;
    int o0 = lane & 15;
    int bl = lane >> 4;
    int btl = wid * 4 + bl * 2;          // local bt pair (btl, btl+1)
    for (int iter = 0; iter < 16; iter++) {
        int bt0 = chunk * 512 + iter * 32;
        __syncthreads();
        #pragma unroll
        for (int r = 0; r < 2; r++) {
            int idx = tid + r * 256;
            int bti = idx >> 4, c = idx & 15;
            int bt  = bt0 + bti;
            float4 st = g_stats[BB + (bt >> 5)];
            float2 z  = g_p1[(bt * F1 + f) * CI + c];
            sxb[idx] = make_float2(z.x * st.x + st.y, z.y * st.x + st.z);
        }
        __syncthreads();
        float r00 = 0.f, i00 = 0.f, r01 = 0.f, i01 = 0.f;
        float r10 = 0.f, i10 = 0.f, r11 = 0.f, i11 = 0.f;
        #pragma unroll
        for (int c = 0; c < CI; c++) {
            float2 x0 = sxb[btl * CI + c];
            float2 x1 = sxb[(btl + 1) * CI + c];
            float2 k0 = sfk[c * CO + o0];
            float2 k1 = sfk[c * CO + o0 + 16];
            r00 += x0.x * k0.x - x0.y * k0.y;  i00 += x0.x * k0.y + x0.y * k0.x;
            r01 += x0.x * k1.x - x0.y * k1.y;  i01 += x0.x * k1.y + x0.y * k1.x;
            r10 += x1.x * k0.x - x1.y * k0.y;  i10 += x1.x * k0.y + x1.y * k0.x;
            r11 += x1.x * k1.x - x1.y * k1.y;  i11 += x1.x * k1.y + x1.y * k1.x;
        }
        long gb = (long)(bt0 + btl) * F1 + f;
        g_out1[gb * CO + o0]             = make_float2(r00, i00);
        g_out1[gb * CO + o0 + 16]        = make_float2(r01, i01);
        g_out1[(gb + F1) * CO + o0]      = make_float2(r10, i10);
        g_out1[(gb + F1) * CO + o0 + 16] = make_float2(r11, i11);
    }
}

// ===== iSTFT-256 : 128 thr, parity split (jp & 128-jp) + 4j x 4o tiling + bias/relu =====
__global__ void k_istft1(const float* __restrict__ pbias, float* __restrict__ y) {
    extern __shared__ char smraw[];
    float2* sX  = (float2*)smraw;            // F1*CO
    float2* tw  = sX + F1 * CO;              // 256
    float*  sfr = (float*)(tw + 256);        // 256*33 padded

    int tid = threadIdx.x;
    int b = blockIdx.x >> 5, t = blockIdx.x & 31;
    int fb = (b * T1 + t) * (F1 * CO);
    for (int i = tid; i < F1 * CO; i += 128) sX[i] = g_out1[fb + i];
    for (int i = tid; i < 256; i += 128) {
        float s, c; sincospif(i * (1.0f / 128.0f), &s, &c);
        tw[i] = make_float2(c, s);
    }
    __syncthreads();
    const float inv = 1.0f / 256.0f;
    int u  = tid >> 3;        // jp = u + 16k, k=0..3 (jp in 0..63)
    int og = tid & 7;         // o = og + 8m
    float Ce[4][4], Co[4][4], Se[4][4], So[4][4];
    int io[4], ie[4], jq[4];
    #pragma unroll
    for (int k = 0; k < 4; k++) {
        jq[k] = u + 16 * k;
        io[k] = jq[k];
        ie[k] = 0;
        #pragma unroll
        for (int m = 0; m < 4; m++) { Ce[k][m] = Co[k][m] = Se[k][m] = So[k][m] = 0.f; }
    }
    const float2* pX = sX + og;
    // h = 0 : f = 1 (odd only)
    {
        float2 X[4];
        #pragma unroll
        for (int m = 0; m < 4; m++) X[m] = pX[CO + 8 * m];
        #pragma unroll
        for (int k = 0; k < 4; k++) {
            float2 w = tw[io[k]];
            #pragma unroll
            for (int m = 0; m < 4; m++) {
                Co[k][m] += X[m].x * w.x;
                So[k][m] += X[m].y * w.y;
            }
        }
    }
    #pragma unroll 2
    for (int h = 1; h < 64; h++) {
        float2 Xe[4], Xo[4];
        #pragma unroll
        for (int m = 0; m < 4; m++) {
            Xe[m] = pX[(2 * h) * CO + 8 * m];
            Xo[m] = pX[(2 * h + 1) * CO + 8 * m];
        }
        #pragma unroll
        for (int k = 0; k < 4; k++) {
            ie[k] = (ie[k] + 2 * jq[k]) & 255;
            io[k] = (io[k] + 2 * jq[k]) & 255;
            float2 we = tw[ie[k]];
            float2 wo = tw[io[k]];
            #pragma unroll
            for (int m = 0; m < 4; m++) {
                Ce[k][m] += Xe[m].x * we.x;  Se[k][m] += Xe[m].y * we.y;
                Co[k][m] += Xo[m].x * wo.x;  So[k][m] += Xo[m].y * wo.y;
            }
        }
    }
    float sg = (u & 1) ? -1.f : 1.f;     // parity(jp)=parity(u) for all k
    #pragma unroll
    for (int m = 0; m < 4; m++) {
        int o = og + 8 * m;
        float x0 = sX[o].x, xN = sX[128 * CO + o].x;
        float bs = x0 + sg * xN;
        #pragma unroll
        for (int k = 0; k < 4; k++) {
            int j = jq[k];
            float A = Ce[k][m], B = Co[k][m], D = Se[k][m], E = So[k][m];
            float cp = A + B, cm = A - B, sp = D + E, sm = D - E;
            sfr[j * 33 + o] = (bs + 2.f * (cp - sp)) * inv;
            if (j) sfr[(256 - j) * 33 + o] = (bs + 2.f * (cp + sp)) * inv;
            sfr[(128 - j) * 33 + o] = (bs + 2.f * (cm + sm)) * inv;
            if (j) sfr[(128 + j) * 33 + o] = (bs + 2.f * (cm - sm)) * inv;
        }
    }
    // jp = 64 special: rows 64 and 192
    if (tid < 32) {
        int o = tid;
        float Sr = 0.f, Si = 0.f;
        #pragma unroll 4
        for (int g = 1; g < 64; g++) {
            float v = sX[(2 * g) * CO + o].x;
            Sr += (g & 1) ? -v : v;
        }
        #pragma unroll 4
        for (int g = 0; g < 64; g++) {
            float v = sX[(2 * g + 1) * CO + o].y;
            Si += (g & 1) ? -v : v;
        }
        float bs = sX[o].x + sX[128 * CO + o].x;
        sfr[64 * 33 + o]  = (bs + 2.f * (Sr - Si)) * inv;
        sfr[192 * 33 + o] = (bs + 2.f * (Sr + Si)) * inv;
    }
    __syncthreads();
    for (int i = tid; i < N1 * CO; i += 128) {
        int o = i >> 8, j = i & 255;
        float v = sfr[j * 33 + o];
        int s = (t == 0) ? ((j >= 128) ? (j - 128) : (8064 + j)) : (t * 256 + j - 128);
        y[(b * 64 + 32 + o) * LEN + s] = fmaxf(v + pbias[32 + o], 0.f);
    }
}

// ================= launcher =================
extern "C" void kernel_launch(void* const* d_in, const int* in_sizes, int n_in,
                              void* d_out, int out_size) {
    const float* x        = (const float*)d_in[0];
    const float* bn_gamma = (const float*)d_in[1];
    const float* bn_beta  = (const float*)d_in[2];
    const float* mk_r     = (const float*)d_in[3];
    const float* mk_i     = (const float*)d_in[4];
    const float* mb_r     = (const float*)d_in[5];
    const float* mb_i     = (const float*)d_in[6];
    const float* fk0_r    = (const float*)d_in[7];
    const float* fk0_i    = (const float*)d_in[8];
    const float* fk1_r    = (const float*)d_in[9];
    const float* fk1_i    = (const float*)d_in[10];
    const float* pbias    = (const float*)d_in[11];
    float* y = (float*)d_out;

    const int SMEM0 = (F0 * CI * CO + F0 * CI + F0 * CO + 64) * 8 + 64 * 33 * 4;   // head0
    const int SMEM2 = (F1 * CO + 256) * 8 + 256 * 33 * 4;                           // istft1

    cudaFuncSetAttribute(k_head0,  cudaFuncAttributeMaxDynamicSharedMemorySize, SMEM0);
    cudaFuncSetAttribute(k_istft1, cudaFuncAttributeMaxDynamicSharedMemorySize, SMEM2);

    k_stft0 <<<BB * T0, 128>>>(x);
    k_stft1 <<<BB * T1, 128>>>(x);
    k_merge <<<(BB * T1 * F0 * CI) / 256, 256>>>(mk_r, mk_i, mb_r, mb_i);
    k_stats_part<<<1024, 256>>>();
    k_stats_fin <<<1, 128>>>(bn_gamma, bn_beta);
    k_head0 <<<BB * 8, 256, SMEM0>>>(fk0_r, fk0_i, pbias, y);
    k_head1e<<<F1 * 4, 256>>>(fk1_r, fk1_i);
    k_istft1<<<BB * T1, 128, SMEM2>>>(pbias, y);
}